// round 13
// baseline (speedup 1.0000x reference)
#include <cuda_runtime.h>
#include <math.h>

#define KNOTS   1024
#define S_PTS   4095
#define INV_SAMP (1.0f / 4096.0f)
#define INV_S    (1.0f / (float)S_PTS)
#define NMOM   6            // Taylor n = 0..5 (gate 0.1 -> err <= 1.4e-9/knot)
#define GATE   0.1f
#define NBLK   8
#define NTHR   512
#define TGUARD 13.3f        // conservative: e<88 <=> |a|<13.2665

// ---------------- scratch (device globals; slow path only) -------------------
__device__ float g_smear[(size_t)KNOTS * S_PTS];
__device__ float g_rowsum[KNOTS], g_coef1[KNOTS];
__device__ float g_cwp[NBLK * KNOTS];
__device__ float g_Rp[NBLK];
__device__ unsigned g_count = 0;   // self-resetting per barrier episode
__device__ unsigned g_gen   = 0;   // monotone across graph replays

// ---------------- warp helpers -------------------------------------------------
__device__ __forceinline__ float warp_sum(float v) {
    #pragma unroll
    for (int o = 16; o > 0; o >>= 1) v += __shfl_xor_sync(0xFFFFFFFFu, v, o);
    return v;
}
__device__ __forceinline__ float warp_max(float v) {
    #pragma unroll
    for (int o = 16; o > 0; o >>= 1) v = fmaxf(v, __shfl_xor_sync(0xFFFFFFFFu, v, o));
    return v;
}
__device__ __forceinline__ float warp_min(float v) {
    #pragma unroll
    for (int o = 16; o > 0; o >>= 1) v = fminf(v, __shfl_xor_sync(0xFFFFFFFFu, v, o));
    return v;
}
// broadcast block sum for the slow path (512 threads = 16 warps)
__device__ __forceinline__ float block_sum_b(float v, float* red) {
    int tid = threadIdx.x;
    v = warp_sum(v);
    if ((tid & 31) == 0) red[tid >> 5] = v;
    __syncthreads();
    if (tid == 0) {
        float r = red[0];
        #pragma unroll
        for (int w = 1; w < NTHR / 32; w++) r += red[w];
        red[16] = r;
    }
    __syncthreads();
    float o = red[16];
    __syncthreads();
    return o;
}

// conservative upper bound of exp(t): 1+t+t^2 for t<=1 (valid for all t<=1),
// inflated __expf otherwise. NaN propagates -> comparisons fail -> slow path.
__device__ __forceinline__ float exp_ub(float t) {
    return (t <= 1.0f) ? fmaf(t, t + 1.0f, 1.0f) : __expf(t) * 1.01f;
}

// ---------------- software grid barrier (slow path only) ---------------------
__device__ __forceinline__ void grid_barrier() {
    __threadfence();
    __syncthreads();
    if (threadIdx.x == 0) {
        unsigned my = *((volatile unsigned*)&g_gen);
        if (atomicAdd(&g_count, 1u) == NBLK - 1) {
            g_count = 0;
            __threadfence();
            *((volatile unsigned*)&g_gen) = my + 1;
        } else {
            while (*((volatile unsigned*)&g_gen) == my) { }
        }
        __threadfence();
    }
    __syncthreads();
}

// ======================= the single kernel ====================================
__global__ __launch_bounds__(NTHR, 1)
void knot_one(const float* __restrict__ x,
              const float* __restrict__ sw,
              const float* __restrict__ kmean,
              const float* __restrict__ klow,
              const float* __restrict__ khigh,
              const float* __restrict__ emean,
              const float* __restrict__ elow,
              const float* __restrict__ ehigh,
              const float* __restrict__ pol,
              float* __restrict__ out) {
    // pool (36 KB) aliased per phase:
    //   fast reduce:  buf[16 * 512]          (32 KB, 14 rows used)
    //   slow mix:     9 arrays x 1024        (36 KB)
    //   slow output:  6 arrays x 1024        (24 KB)
    __shared__ float pool[9216];
    __shared__ float red[17];
    __shared__ float s_res[16];
    __shared__ float s_cf[2 * NMOM];
    __shared__ int   s_fastenv;

    const int tid  = threadIdx.x;
    const int bid  = blockIdx.x;
    const int warp = tid >> 5, lane = tid & 31;

    // =============== phase 1: vectorized loads, 2 knots, 4 MUFU/knot =========
    const float2 swv  = *(const float2*)sw;
    const float lower = swv.x, upper = swv.y;
    const float2 xk2  = ((const float2*)x)[tid];
    const float2 kml2 = ((const float2*)klow)[tid];
    const float2 kmh2 = ((const float2*)khigh)[tid];
    const float2 kmn2 = ((const float2*)kmean)[tid];
    const float2 eml2 = ((const float2*)emean)[tid];
    const float2 eln2 = ((const float2*)elow)[tid];
    const float2 ehn2 = ((const float2*)ehigh)[tid];

    float B2[2], v0c2[2], clo2[2], chi2[2], em2[2];
    int noncst = 0;
    #pragma unroll
    for (int q = 0; q < 2; q++) {
        float xk   = q ? xk2.y  : xk2.x;
        float kml  = q ? kml2.y : kml2.x;
        float kmh  = q ? kmh2.y : kmh2.x;
        float mean = q ? kmn2.y : kmn2.x;
        float xlow  = (1.0f - lower) * xk;
        float xstep = ((upper - lower) * xk) * INV_SAMP;
        int   cst   = (xstep == 0.0f) ? 1 : 0;
        float d     = xlow - mean;
        float r0    = __expf(-((xlow <= mean) ? kml : kmh));   // MUFU 1
        float a0    = d * r0;
        float v0    = __expf(-0.5f * a0 * a0);                  // MUFU 2
        float B     = (float)S_PTS * v0;
        B2[q]   = B;
        v0c2[q] = cst ? v0 : 0.0f;
        if (!cst) noncst = 1;

        float highs = (1.0f + upper) * xk;
        float erlw = __expf(-xlow);                              // MUFU 3
        float erhg = __expf(-highs);                             // MUFU 4
        float hlo = xk * erlw, hhi = xk * erhg;
        clo2[q] = 0.5f * hlo * hlo;
        chi2[q] = 0.5f * hhi * hhi;

        em2[q]  = q ? eml2.y : eml2.x;
    }

    // =============== phase 2: single batched 14-quantity reduction ===========
    // q 0..4 : low moments n=1..5 | q 5..9 : high moments | q10: v0 sum
    // q11: cmax (max) | q12: Bmin (min) | q13: Bmax (max)
    {
        float* buf = pool;
        float pl0 = clo2[0], pl1 = clo2[1], ph0 = chi2[0], ph1 = chi2[1];
        #pragma unroll
        for (int n = 1; n <= 5; n++) {
            buf[(n - 1) * NTHR + tid] = pl0 + pl1;
            buf[(4 + n) * NTHR + tid] = ph0 + ph1;
            pl0 *= clo2[0]; pl1 *= clo2[1];
            ph0 *= chi2[0]; ph1 *= chi2[1];
        }
        buf[10 * NTHR + tid] = v0c2[0] + v0c2[1];
        buf[11 * NTHR + tid] = fmaxf(fmaxf(clo2[0], chi2[0]),
                                     fmaxf(clo2[1], chi2[1]));
        buf[12 * NTHR + tid] = fminf(B2[0], B2[1]);
        buf[13 * NTHR + tid] = fmaxf(B2[0], B2[1]);
    }
    int anyvar = __syncthreads_or(noncst);   // barrier #1 (covers buf writes)

    if (warp < 14) {
        const float* b = pool + warp * NTHR;
        float a0 = b[lane], a1 = b[lane + 32], a2 = b[lane + 64], a3 = b[lane + 96];
        float a4 = b[lane + 128], a5 = b[lane + 160], a6 = b[lane + 192], a7 = b[lane + 224];
        float a8 = b[lane + 256], a9 = b[lane + 288], aA = b[lane + 320], aB = b[lane + 352];
        float aC = b[lane + 384], aD = b[lane + 416], aE = b[lane + 448], aF = b[lane + 480];
        float v;
        if (warp == 11 || warp == 13) {       // max
            v = fmaxf(fmaxf(fmaxf(a0, a1), fmaxf(a2, a3)),
                      fmaxf(fmaxf(a4, a5), fmaxf(a6, a7)));
            v = fmaxf(v, fmaxf(fmaxf(fmaxf(a8, a9), fmaxf(aA, aB)),
                               fmaxf(fmaxf(aC, aD), fmaxf(aE, aF))));
            v = warp_max(v);
        } else if (warp == 12) {              // min
            v = fminf(fminf(fminf(a0, a1), fminf(a2, a3)),
                      fminf(fminf(a4, a5), fminf(a6, a7)));
            v = fminf(v, fminf(fminf(fminf(a8, a9), fminf(aA, aB)),
                               fminf(fminf(aC, aD), fminf(aE, aF))));
            v = warp_min(v);
        } else {                              // sum
            v = ((a0 + a1) + (a2 + a3)) + ((a4 + a5) + (a6 + a7))
              + ((a8 + a9) + (aA + aB)) + ((aC + aD) + (aE + aF));
            v = warp_sum(v);
        }
        if (lane == 0) s_res[warp] = v;
    }
    __syncthreads();                          // barrier #2 (s_res visible)

    // =============== phase 3: no-pass screen (exp-free) + coefficients =======
    const float Bmin = s_res[12], Bmax = s_res[13];
    int pass = 0;
    #pragma unroll
    for (int q = 0; q < 2; q++) {
        float ubl = exp_ub(q ? eln2.y : eln2.x);
        float ubh = exp_ub(q ? ehn2.y : ehn2.x);
        float lo = em2[q] - TGUARD * ubl;   // lower bound of true lo
        float hi = em2[q] + TGUARD * ubh;   // upper bound of true hi
        float cminj = Bmin * B2[q] * INV_S;
        float cmaxj = Bmax * B2[q] * INV_S;
        // NaN-safe: NaN comparisons are false -> pass=1 -> slow path
        if (!(cmaxj < lo) && !(cminj > hi)) pass = 1;
    }

    if (tid < 2 * NMOM) {
        const float invfact[NMOM] = {1.0f, 1.0f, 0.5f, 1.0f/6.0f, 1.0f/24.0f,
                                     1.0f/120.0f};
        int side = (tid >= NMOM) ? 1 : 0;
        int n    = tid - side * NMOM;
        s_cf[tid] = (n == 0) ? (float)KNOTS
                             : s_res[side * 5 + (n - 1)] * invfact[n];
        if (tid == 0) {
            float phi0 = -lower;
            float phiE = fmaf((float)(S_PTS - 1) * INV_SAMP, lower + upper, -lower);
            float tmax = fmaxf(phi0 * phi0, phiE * phiE);
            float gate = s_res[11] * tmax;
            s_fastenv = (gate <= GATE) ? 1 : 0;   // NaN -> slow env loop
        }
    }
    float R = (float)(KNOTS - 1) * s_res[10];      // Rbase
    // barrier #3: or-result + visibility of s_cf / s_fastenv
    const int slow = __syncthreads_or(pass) | anyvar;

    // ======================= SLOW PATH (general correctness) =================
    float* s_w    = pool;
    float* s_glow = pool + 1024;
    float* s_gd   = pool + 2048;
    float* s_grl  = pool + 3072;
    float* s_grh  = pool + 4096;
    float* s_cst  = pool + 5120;

    if (slow) {
        float* sA   = pool;
        float* sB   = pool + 1024;
        float* sV0c = pool + 2048;
        float* sSvj = pool + 3072;
        float* sCb  = pool + 4096;
        float* sEm  = pool + 5120;
        float* sErl = pool + 6144;
        float* sErh = pool + 7168;
        float* sCw  = pool + 8192;

        const float2 pol2 = ((const float2*)pol)[tid];
        #pragma unroll
        for (int q = 0; q < 2; q++) {
            int k = 2 * tid + q;
            float sp, cp;
            __sincosf(q ? pol2.y : pol2.x, &sp, &cp);
            sA[k]   = B2[q];
            sB[k]   = B2[q];
            sV0c[k] = v0c2[q];
            sSvj[k] = sp * v0c2[q];
            sCb[k]  = cp * B2[q];
            sEm[k]  = em2[q];
            sErl[k] = __expf(-(q ? eln2.y : eln2.x));   // exact exp(-elow)
            sErh[k] = __expf(-(q ? ehn2.y : ehn2.x));   // exact exp(-ehigh)
            sCw[k]  = 0.0f;
        }
        __syncthreads();

        // non-constant knots: true A via S-loop; owning block stores smear rows
        if (anyvar) {
            for (int k = 0; k < KNOTS; k++) {
                float xk = x[k];
                float xstep = ((upper - lower) * xk) * INV_SAMP;
                if (xstep == 0.0f) continue;
                float xlow = (1.0f - lower) * xk;
                float rl = __expf(-klow[k]);
                float rh = __expf(-khigh[k]);
                float mean = kmean[k];
                bool own = (bid == (k >> 7));    // 128 knots per owning block
                float* __restrict__ row = &g_smear[(size_t)k * S_PTS];
                float acc = 0.0f;
                for (int s = tid; s < S_PTS; s += NTHR) {
                    float gv = fmaf(xstep, (float)s, xlow);
                    float dd = gv - mean;
                    float rr = (gv <= mean) ? rl : rh;
                    float aa = dd * rr;
                    float vv = __expf(-0.5f * aa * aa);
                    if (own) row[s] = vv;
                    acc += vv;
                }
                float tot = block_sum_b(acc, red);
                if (tid == 0) sA[k] = tot;
                __syncthreads();
            }
        }

        // mix: 128 rows/block = 16 warps x 8 rows
        float rp = 0.0f;
        #pragma unroll
        for (int rr = 0; rr < 8; rr++) {
            int i = bid * 128 + rr * 16 + warp;
            float AiS  = sA[i] * INV_S;
            float Bi   = sB[i];
            float v0ci = sV0c[i];
            float rs = 0.0f, c1 = 0.0f;
            for (int j = lane; j < KNOTS; j += 32) {
                float corr = AiS * sA[j];
                float em = sEm[j];
                float dd = corr - em;
                float r  = (corr <= em) ? sErl[j] : sErh[j];
                float a  = dd * r;
                float e  = 0.5f * a * a;
                if (e < 88.0f) {
                    float m = __expf(-e);
                    if (j == i) m = 0.0f;
                    float cb = sCb[j];
                    rs += m;
                    c1 += m * cb;
                    rp += m * (v0ci * (cb - 1.0f) + Bi * sSvj[j]);
                    float v = Bi * m;
                    if (v != 0.0f) atomicAdd(&sCw[j], v);
                }
            }
            rs = warp_sum(rs);
            c1 = warp_sum(c1);
            if (lane == 0) { g_rowsum[i] = rs; g_coef1[i] = c1; }
        }
        float rpt = block_sum_b(rp, red);
        if (tid == 0) g_Rp[bid] = rpt;
        __syncthreads();
        #pragma unroll
        for (int q = 0; q < 2; q++) {
            int k = 2 * tid + q;
            g_cwp[bid * KNOTS + k] = sCw[k];
        }

        grid_barrier();

        #pragma unroll
        for (int p = 0; p < NBLK; p++) R += g_Rp[p];

        __syncthreads();
        #pragma unroll
        for (int q = 0; q < 2; q++) {
            int k = 2 * tid + q;
            float xk = x[k];
            float xlow  = (1.0f - lower) * xk;
            float xstep = ((upper - lower) * xk) * INV_SAMP;
            float cw = 0.0f;
            #pragma unroll
            for (int p = 0; p < NBLK; p++) cw += g_cwp[p * KNOTS + k];
            float w = g_coef1[k] + (float)(KNOTS - 1) - g_rowsum[k]
                    + __sinf(pol[k]) * cw;
            float highs = (1.0f + upper) * xk;
            s_w[k]    = w;
            s_cst[k]  = (xstep == 0.0f) ? 1.0f : 0.0f;
            s_glow[k] = xlow;
            s_gd[k]   = highs - xlow;
            s_grl[k]  = __expf(-xlow);
            s_grh[k]  = __expf(-highs);
        }
        __syncthreads();
    } else if (!s_fastenv) {
        // fast path but envelope needs the exact per-knot loop
        __syncthreads();   // buf dead
        #pragma unroll
        for (int q = 0; q < 2; q++) {
            int k = 2 * tid + q;
            float xk = (q ? xk2.y : xk2.x);
            float xlow  = (1.0f - lower) * xk;
            float highs = (1.0f + upper) * xk;
            s_glow[k] = xlow;
            s_gd[k]   = highs - xlow;
            s_grl[k]  = __expf(-xlow);
            s_grh[k]  = __expf(-highs);
        }
        __syncthreads();
    }

    // ======================= output (1 sample / thread) ======================
    int s = bid * NTHR + tid;
    if (s >= S_PTS) return;

    float xi  = (float)s * INV_SAMP;
    float phi = fmaf(xi, lower + upper, -lower);
    float t   = phi * phi;

    float env;
    if (s_fastenv) {
        const float* cf = s_cf + ((phi <= 0.0f) ? 0 : NMOM);
        float u = -t;
        env = cf[NMOM - 1];
        #pragma unroll
        for (int n = NMOM - 2; n >= 0; n--) env = fmaf(env, u, cf[n]);
    } else {
        env = 0.0f;
        for (int k = 0; k < KNOTS; k++) {
            float mn = x[k];
            float gv = fmaf(s_gd[k], xi, s_glow[k]);
            float dd = gv - mn;
            float r  = (gv <= mn) ? s_grl[k] : s_grh[k];
            float a  = dd * r;
            env += __expf(-0.5f * a * a);
        }
    }

    float res = R;
    if (slow && anyvar) {
        for (int k = 0; k < KNOTS; k++) {
            if (s_cst[k] == 0.0f)
                res = fmaf(s_w[k], g_smear[(size_t)k * S_PTS + s], res);
        }
    }
    out[s] = env * res;
}

// ---------------- launch ------------------------------------------------------
extern "C" void kernel_launch(void* const* d_in, const int* in_sizes, int n_in,
                              void* d_out, int out_size) {
    const float* x     = (const float*)d_in[0];
    const float* sw    = (const float*)d_in[1];
    const float* kmean = (const float*)d_in[2];
    const float* klow  = (const float*)d_in[3];
    const float* khigh = (const float*)d_in[4];
    const float* emean = (const float*)d_in[5];
    const float* elow  = (const float*)d_in[6];
    const float* ehigh = (const float*)d_in[7];
    const float* pol   = (const float*)d_in[8];
    float* out = (float*)d_out;

    knot_one<<<NBLK, NTHR>>>(x, sw, kmean, klow, khigh, emean, elow, ehigh, pol, out);
}

// round 14
// speedup vs baseline: 1.0338x; 1.0338x over previous
#include <cuda_runtime.h>
#include <math.h>

#define KNOTS   1024
#define S_PTS   4095
#define INV_SAMP (1.0f / 4096.0f)
#define INV_S    (1.0f / (float)S_PTS)
#define NMOM   6            // Taylor n = 0..5 (gate 0.1 -> err <= 1.4e-9/knot)
#define GATE   0.1f
#define NBLK   8
#define NTHR   512
#define TGUARD 13.3f        // conservative: e<88 <=> |a|<13.2665

// ---------------- scratch (device globals; slow path only) -------------------
__device__ float g_smear[(size_t)KNOTS * S_PTS];
__device__ float g_rowsum[KNOTS], g_coef1[KNOTS];
__device__ float g_cwp[NBLK * KNOTS];
__device__ float g_Rp[NBLK];
__device__ unsigned g_count = 0;   // self-resetting per barrier episode
__device__ unsigned g_gen   = 0;   // monotone across graph replays

// ---------------- warp helpers -------------------------------------------------
__device__ __forceinline__ float warp_sum(float v) {
    #pragma unroll
    for (int o = 16; o > 0; o >>= 1) v += __shfl_xor_sync(0xFFFFFFFFu, v, o);
    return v;
}
__device__ __forceinline__ float warp_max(float v) {
    #pragma unroll
    for (int o = 16; o > 0; o >>= 1) v = fmaxf(v, __shfl_xor_sync(0xFFFFFFFFu, v, o));
    return v;
}
__device__ __forceinline__ float warp_min(float v) {
    #pragma unroll
    for (int o = 16; o > 0; o >>= 1) v = fminf(v, __shfl_xor_sync(0xFFFFFFFFu, v, o));
    return v;
}
// broadcast block sum for the slow path (512 threads = 16 warps)
__device__ __forceinline__ float block_sum_b(float v, float* red) {
    int tid = threadIdx.x;
    v = warp_sum(v);
    if ((tid & 31) == 0) red[tid >> 5] = v;
    __syncthreads();
    if (tid == 0) {
        float r = red[0];
        #pragma unroll
        for (int w = 1; w < NTHR / 32; w++) r += red[w];
        red[16] = r;
    }
    __syncthreads();
    float o = red[16];
    __syncthreads();
    return o;
}

// conservative upper bound of exp(t): 1+t+t^2 for t<=1 (valid for all t<=1),
// inflated __expf otherwise. NaN propagates -> comparisons fail -> slow path.
__device__ __forceinline__ float exp_ub(float t) {
    return (t <= 1.0f) ? fmaf(t, t + 1.0f, 1.0f) : __expf(t) * 1.01f;
}

// ---------------- software grid barrier (slow path only) ---------------------
__device__ __forceinline__ void grid_barrier() {
    __threadfence();
    __syncthreads();
    if (threadIdx.x == 0) {
        unsigned my = *((volatile unsigned*)&g_gen);
        if (atomicAdd(&g_count, 1u) == NBLK - 1) {
            g_count = 0;
            __threadfence();
            *((volatile unsigned*)&g_gen) = my + 1;
        } else {
            while (*((volatile unsigned*)&g_gen) == my) { }
        }
        __threadfence();
    }
    __syncthreads();
}

// ======================= the single kernel ====================================
__global__ __launch_bounds__(NTHR, 1)
void knot_one(const float* __restrict__ x,
              const float* __restrict__ sw,
              const float* __restrict__ kmean,
              const float* __restrict__ klow,
              const float* __restrict__ khigh,
              const float* __restrict__ emean,
              const float* __restrict__ elow,
              const float* __restrict__ ehigh,
              const float* __restrict__ pol,
              float* __restrict__ out) {
    // pool (36 KB) aliased per phase:
    //   fast reduce:  buf[16 * 512]          (32 KB, 14 rows used)
    //   slow mix:     9 arrays x 1024        (36 KB)
    //   slow output:  6 arrays x 1024        (24 KB)
    __shared__ float pool[9216];
    __shared__ float red[17];
    __shared__ float s_res[16];
    __shared__ float s_cf[2 * NMOM];
    __shared__ int   s_fastenv;

    const int tid  = threadIdx.x;
    const int bid  = blockIdx.x;
    const int warp = tid >> 5, lane = tid & 31;

    // =============== phase 1: vectorized loads, 2 knots, 4 MUFU/knot =========
    const float2 swv  = *(const float2*)sw;
    const float lower = swv.x, upper = swv.y;
    const float2 xk2  = ((const float2*)x)[tid];
    const float2 kml2 = ((const float2*)klow)[tid];
    const float2 kmh2 = ((const float2*)khigh)[tid];
    const float2 kmn2 = ((const float2*)kmean)[tid];
    const float2 eml2 = ((const float2*)emean)[tid];
    const float2 eln2 = ((const float2*)elow)[tid];
    const float2 ehn2 = ((const float2*)ehigh)[tid];

    float B2[2], v0c2[2], clo2[2], chi2[2], em2[2];
    int noncst = 0;
    #pragma unroll
    for (int q = 0; q < 2; q++) {
        float xk   = q ? xk2.y  : xk2.x;
        float kml  = q ? kml2.y : kml2.x;
        float kmh  = q ? kmh2.y : kmh2.x;
        float mean = q ? kmn2.y : kmn2.x;
        float xlow  = (1.0f - lower) * xk;
        float xstep = ((upper - lower) * xk) * INV_SAMP;
        int   cst   = (xstep == 0.0f) ? 1 : 0;
        float d     = xlow - mean;
        float r0    = __expf(-((xlow <= mean) ? kml : kmh));   // MUFU 1
        float a0    = d * r0;
        float v0    = __expf(-0.5f * a0 * a0);                  // MUFU 2
        float B     = (float)S_PTS * v0;
        B2[q]   = B;
        v0c2[q] = cst ? v0 : 0.0f;
        if (!cst) noncst = 1;

        float highs = (1.0f + upper) * xk;
        float erlw = __expf(-xlow);                              // MUFU 3
        float erhg = __expf(-highs);                             // MUFU 4
        float hlo = xk * erlw, hhi = xk * erhg;
        clo2[q] = 0.5f * hlo * hlo;
        chi2[q] = 0.5f * hhi * hhi;

        em2[q]  = q ? eml2.y : eml2.x;
    }

    // =============== phase 2: single batched 14-quantity reduction ===========
    // q 0..4 : low moments n=1..5 | q 5..9 : high moments | q10: v0 sum
    // q11: cmax (max) | q12: Bmin (min) | q13: Bmax (max)
    {
        float* buf = pool;
        float pl0 = clo2[0], pl1 = clo2[1], ph0 = chi2[0], ph1 = chi2[1];
        #pragma unroll
        for (int n = 1; n <= 5; n++) {
            buf[(n - 1) * NTHR + tid] = pl0 + pl1;
            buf[(4 + n) * NTHR + tid] = ph0 + ph1;
            pl0 *= clo2[0]; pl1 *= clo2[1];
            ph0 *= chi2[0]; ph1 *= chi2[1];
        }
        buf[10 * NTHR + tid] = v0c2[0] + v0c2[1];
        buf[11 * NTHR + tid] = fmaxf(fmaxf(clo2[0], chi2[0]),
                                     fmaxf(clo2[1], chi2[1]));
        buf[12 * NTHR + tid] = fminf(B2[0], B2[1]);
        buf[13 * NTHR + tid] = fmaxf(B2[0], B2[1]);
    }
    int anyvar = __syncthreads_or(noncst);   // barrier #1 (covers buf writes)

    if (warp < 14) {
        const float* b = pool + warp * NTHR;
        float a0 = b[lane], a1 = b[lane + 32], a2 = b[lane + 64], a3 = b[lane + 96];
        float a4 = b[lane + 128], a5 = b[lane + 160], a6 = b[lane + 192], a7 = b[lane + 224];
        float a8 = b[lane + 256], a9 = b[lane + 288], aA = b[lane + 320], aB = b[lane + 352];
        float aC = b[lane + 384], aD = b[lane + 416], aE = b[lane + 448], aF = b[lane + 480];
        float v;
        if (warp == 11 || warp == 13) {       // max
            v = fmaxf(fmaxf(fmaxf(a0, a1), fmaxf(a2, a3)),
                      fmaxf(fmaxf(a4, a5), fmaxf(a6, a7)));
            v = fmaxf(v, fmaxf(fmaxf(fmaxf(a8, a9), fmaxf(aA, aB)),
                               fmaxf(fmaxf(aC, aD), fmaxf(aE, aF))));
            v = warp_max(v);
        } else if (warp == 12) {              // min
            v = fminf(fminf(fminf(a0, a1), fminf(a2, a3)),
                      fminf(fminf(a4, a5), fminf(a6, a7)));
            v = fminf(v, fminf(fminf(fminf(a8, a9), fminf(aA, aB)),
                               fminf(fminf(aC, aD), fminf(aE, aF))));
            v = warp_min(v);
        } else {                              // sum
            v = ((a0 + a1) + (a2 + a3)) + ((a4 + a5) + (a6 + a7))
              + ((a8 + a9) + (aA + aB)) + ((aC + aD) + (aE + aF));
            v = warp_sum(v);
        }
        if (lane == 0) s_res[warp] = v;
    }
    __syncthreads();                          // barrier #2 (s_res visible)

    // =============== phase 3: no-pass screen (exp-free) + coefficients =======
    const float Bmin = s_res[12], Bmax = s_res[13];
    int pass = 0;
    #pragma unroll
    for (int q = 0; q < 2; q++) {
        float ubl = exp_ub(q ? eln2.y : eln2.x);
        float ubh = exp_ub(q ? ehn2.y : ehn2.x);
        float lo = em2[q] - TGUARD * ubl;   // lower bound of true lo
        float hi = em2[q] + TGUARD * ubh;   // upper bound of true hi
        float cminj = Bmin * B2[q] * INV_S;
        float cmaxj = Bmax * B2[q] * INV_S;
        // NaN-safe: NaN comparisons are false -> pass=1 -> slow path
        if (!(cmaxj < lo) && !(cminj > hi)) pass = 1;
    }

    if (tid < 2 * NMOM) {
        const float invfact[NMOM] = {1.0f, 1.0f, 0.5f, 1.0f/6.0f, 1.0f/24.0f,
                                     1.0f/120.0f};
        int side = (tid >= NMOM) ? 1 : 0;
        int n    = tid - side * NMOM;
        s_cf[tid] = (n == 0) ? (float)KNOTS
                             : s_res[side * 5 + (n - 1)] * invfact[n];
        if (tid == 0) {
            float phi0 = -lower;
            float phiE = fmaf((float)(S_PTS - 1) * INV_SAMP, lower + upper, -lower);
            float tmax = fmaxf(phi0 * phi0, phiE * phiE);
            float gate = s_res[11] * tmax;
            s_fastenv = (gate <= GATE) ? 1 : 0;   // NaN -> slow env loop
        }
    }
    float R = (float)(KNOTS - 1) * s_res[10];      // Rbase
    // barrier #3: or-result + visibility of s_cf / s_fastenv
    const int slow = __syncthreads_or(pass) | anyvar;

    // ======================= SLOW PATH (general correctness) =================
    float* s_w    = pool;
    float* s_glow = pool + 1024;
    float* s_gd   = pool + 2048;
    float* s_grl  = pool + 3072;
    float* s_grh  = pool + 4096;
    float* s_cst  = pool + 5120;

    if (slow) {
        float* sA   = pool;
        float* sB   = pool + 1024;
        float* sV0c = pool + 2048;
        float* sSvj = pool + 3072;
        float* sCb  = pool + 4096;
        float* sEm  = pool + 5120;
        float* sErl = pool + 6144;
        float* sErh = pool + 7168;
        float* sCw  = pool + 8192;

        const float2 pol2 = ((const float2*)pol)[tid];
        #pragma unroll
        for (int q = 0; q < 2; q++) {
            int k = 2 * tid + q;
            float sp, cp;
            __sincosf(q ? pol2.y : pol2.x, &sp, &cp);
            sA[k]   = B2[q];
            sB[k]   = B2[q];
            sV0c[k] = v0c2[q];
            sSvj[k] = sp * v0c2[q];
            sCb[k]  = cp * B2[q];
            sEm[k]  = em2[q];
            sErl[k] = __expf(-(q ? eln2.y : eln2.x));   // exact exp(-elow)
            sErh[k] = __expf(-(q ? ehn2.y : ehn2.x));   // exact exp(-ehigh)
            sCw[k]  = 0.0f;
        }
        __syncthreads();

        // non-constant knots: true A via S-loop; owning block stores smear rows
        if (anyvar) {
            for (int k = 0; k < KNOTS; k++) {
                float xk = x[k];
                float xstep = ((upper - lower) * xk) * INV_SAMP;
                if (xstep == 0.0f) continue;
                float xlow = (1.0f - lower) * xk;
                float rl = __expf(-klow[k]);
                float rh = __expf(-khigh[k]);
                float mean = kmean[k];
                bool own = (bid == (k >> 7));    // 128 knots per owning block
                float* __restrict__ row = &g_smear[(size_t)k * S_PTS];
                float acc = 0.0f;
                for (int s = tid; s < S_PTS; s += NTHR) {
                    float gv = fmaf(xstep, (float)s, xlow);
                    float dd = gv - mean;
                    float rr = (gv <= mean) ? rl : rh;
                    float aa = dd * rr;
                    float vv = __expf(-0.5f * aa * aa);
                    if (own) row[s] = vv;
                    acc += vv;
                }
                float tot = block_sum_b(acc, red);
                if (tid == 0) sA[k] = tot;
                __syncthreads();
            }
        }

        // mix: 128 rows/block = 16 warps x 8 rows
        float rp = 0.0f;
        #pragma unroll
        for (int rr = 0; rr < 8; rr++) {
            int i = bid * 128 + rr * 16 + warp;
            float AiS  = sA[i] * INV_S;
            float Bi   = sB[i];
            float v0ci = sV0c[i];
            float rs = 0.0f, c1 = 0.0f;
            for (int j = lane; j < KNOTS; j += 32) {
                float corr = AiS * sA[j];
                float em = sEm[j];
                float dd = corr - em;
                float r  = (corr <= em) ? sErl[j] : sErh[j];
                float a  = dd * r;
                float e  = 0.5f * a * a;
                if (e < 88.0f) {
                    float m = __expf(-e);
                    if (j == i) m = 0.0f;
                    float cb = sCb[j];
                    rs += m;
                    c1 += m * cb;
                    rp += m * (v0ci * (cb - 1.0f) + Bi * sSvj[j]);
                    float v = Bi * m;
                    if (v != 0.0f) atomicAdd(&sCw[j], v);
                }
            }
            rs = warp_sum(rs);
            c1 = warp_sum(c1);
            if (lane == 0) { g_rowsum[i] = rs; g_coef1[i] = c1; }
        }
        float rpt = block_sum_b(rp, red);
        if (tid == 0) g_Rp[bid] = rpt;
        __syncthreads();
        #pragma unroll
        for (int q = 0; q < 2; q++) {
            int k = 2 * tid + q;
            g_cwp[bid * KNOTS + k] = sCw[k];
        }

        grid_barrier();

        #pragma unroll
        for (int p = 0; p < NBLK; p++) R += g_Rp[p];

        __syncthreads();
        #pragma unroll
        for (int q = 0; q < 2; q++) {
            int k = 2 * tid + q;
            float xk = x[k];
            float xlow  = (1.0f - lower) * xk;
            float xstep = ((upper - lower) * xk) * INV_SAMP;
            float cw = 0.0f;
            #pragma unroll
            for (int p = 0; p < NBLK; p++) cw += g_cwp[p * KNOTS + k];
            float w = g_coef1[k] + (float)(KNOTS - 1) - g_rowsum[k]
                    + __sinf(pol[k]) * cw;
            float highs = (1.0f + upper) * xk;
            s_w[k]    = w;
            s_cst[k]  = (xstep == 0.0f) ? 1.0f : 0.0f;
            s_glow[k] = xlow;
            s_gd[k]   = highs - xlow;
            s_grl[k]  = __expf(-xlow);
            s_grh[k]  = __expf(-highs);
        }
        __syncthreads();
    } else if (!s_fastenv) {
        // fast path but envelope needs the exact per-knot loop
        __syncthreads();   // buf dead
        #pragma unroll
        for (int q = 0; q < 2; q++) {
            int k = 2 * tid + q;
            float xk = (q ? xk2.y : xk2.x);
            float xlow  = (1.0f - lower) * xk;
            float highs = (1.0f + upper) * xk;
            s_glow[k] = xlow;
            s_gd[k]   = highs - xlow;
            s_grl[k]  = __expf(-xlow);
            s_grh[k]  = __expf(-highs);
        }
        __syncthreads();
    }

    // ======================= output (1 sample / thread) ======================
    int s = bid * NTHR + tid;
    if (s >= S_PTS) return;

    float xi  = (float)s * INV_SAMP;
    float phi = fmaf(xi, lower + upper, -lower);
    float t   = phi * phi;

    float env;
    if (s_fastenv) {
        const float* cf = s_cf + ((phi <= 0.0f) ? 0 : NMOM);
        float u = -t;
        env = cf[NMOM - 1];
        #pragma unroll
        for (int n = NMOM - 2; n >= 0; n--) env = fmaf(env, u, cf[n]);
    } else {
        env = 0.0f;
        for (int k = 0; k < KNOTS; k++) {
            float mn = x[k];
            float gv = fmaf(s_gd[k], xi, s_glow[k]);
            float dd = gv - mn;
            float r  = (gv <= mn) ? s_grl[k] : s_grh[k];
            float a  = dd * r;
            env += __expf(-0.5f * a * a);
        }
    }

    float res = R;
    if (slow && anyvar) {
        for (int k = 0; k < KNOTS; k++) {
            if (s_cst[k] == 0.0f)
                res = fmaf(s_w[k], g_smear[(size_t)k * S_PTS + s], res);
        }
    }
    out[s] = env * res;
}

// ---------------- launch ------------------------------------------------------
extern "C" void kernel_launch(void* const* d_in, const int* in_sizes, int n_in,
                              void* d_out, int out_size) {
    const float* x     = (const float*)d_in[0];
    const float* sw    = (const float*)d_in[1];
    const float* kmean = (const float*)d_in[2];
    const float* klow  = (const float*)d_in[3];
    const float* khigh = (const float*)d_in[4];
    const float* emean = (const float*)d_in[5];
    const float* elow  = (const float*)d_in[6];
    const float* ehigh = (const float*)d_in[7];
    const float* pol   = (const float*)d_in[8];
    float* out = (float*)d_out;

    knot_one<<<NBLK, NTHR>>>(x, sw, kmean, klow, khigh, emean, elow, ehigh, pol, out);
}